// round 5
// baseline (speedup 1.0000x reference)
#include <cuda_runtime.h>

// CircleProjectionLayer: z = center + (x-center) * min(1, 1/||x-center||)
// B = 8388608 points, [B,3] f32. HBM stream: 192MB read + 96MB write.
//
// R5: smem-staged transpose to fix warp-level coalescing. R1's layout gave
// each warp LDG a 48B lane stride (12 lines/instr). Here each block owns a
// contiguous 1024-point tile: coalesced 512B-contiguous warp loads ->
// smem -> per-thread regroup (4 whole points) -> smem -> coalesced stores.
// LDS.128 at 48B stride is conflict-free (quarter-warp phasing).

#define TPB   256
#define F4PT  768   // float4s per tile per array (1024 points * 3 / 4... = 768)

__global__ void __launch_bounds__(TPB)
circle_proj_kernel(const float4* __restrict__ x4,
                   const float4* __restrict__ c4,
                   float4* __restrict__ o4)
{
    __shared__ float4 sx[F4PT];
    __shared__ float4 sc[F4PT];
    __shared__ float4 so[F4PT];

    int tid = threadIdx.x;
    long gbase = (long)F4PT * blockIdx.x;

    // Coalesced, front-batched loads (each warp instr = 512B contiguous).
    float4 vx0 = x4[gbase + tid];
    float4 vx1 = x4[gbase + TPB + tid];
    float4 vx2 = x4[gbase + 2 * TPB + tid];
    float4 vc0 = c4[gbase + tid];
    float4 vc1 = c4[gbase + TPB + tid];
    float4 vc2 = c4[gbase + 2 * TPB + tid];

    sx[tid]           = vx0;
    sx[TPB + tid]     = vx1;
    sx[2 * TPB + tid] = vx2;
    sc[tid]           = vc0;
    sc[TPB + tid]     = vc1;
    sc[2 * TPB + tid] = vc2;
    __syncthreads();

    // Regroup: thread owns 4 whole points = float4s [3*tid, 3*tid+3).
    float4 xa = sx[3 * tid + 0];
    float4 xb = sx[3 * tid + 1];
    float4 xc = sx[3 * tid + 2];
    float4 ca = sc[3 * tid + 0];
    float4 cb = sc[3 * tid + 1];
    float4 cc = sc[3 * tid + 2];

    float xs[12] = {xa.x, xa.y, xa.z, xa.w,
                    xb.x, xb.y, xb.z, xb.w,
                    xc.x, xc.y, xc.z, xc.w};
    float cs[12] = {ca.x, ca.y, ca.z, ca.w,
                    cb.x, cb.y, cb.z, cb.w,
                    cc.x, cc.y, cc.z, cc.w};
    float os[12];

#pragma unroll
    for (int p = 0; p < 4; p++) {
        float dx = xs[3 * p + 0] - cs[3 * p + 0];
        float dy = xs[3 * p + 1] - cs[3 * p + 1];
        float dz = xs[3 * p + 2] - cs[3 * p + 2];
        float n2 = fmaf(dx, dx, fmaf(dy, dy, dz * dz));
        // RADIUS = 1: scale = min(1, 1/||d||); rsqrtf(0)=inf -> scale=1 -> z=x.
        float s = fminf(1.0f, rsqrtf(n2));
        os[3 * p + 0] = fmaf(dx, s, cs[3 * p + 0]);
        os[3 * p + 1] = fmaf(dy, s, cs[3 * p + 1]);
        os[3 * p + 2] = fmaf(dz, s, cs[3 * p + 2]);
    }

    so[3 * tid + 0] = make_float4(os[0], os[1], os[2],  os[3]);
    so[3 * tid + 1] = make_float4(os[4], os[5], os[6],  os[7]);
    so[3 * tid + 2] = make_float4(os[8], os[9], os[10], os[11]);
    __syncthreads();

    // Coalesced stores.
    o4[gbase + tid]           = so[tid];
    o4[gbase + TPB + tid]     = so[TPB + tid];
    o4[gbase + 2 * TPB + tid] = so[2 * TPB + tid];
}

extern "C" void kernel_launch(void* const* d_in, const int* in_sizes, int n_in,
                              void* d_out, int out_size)
{
    const float4* x4 = (const float4*)d_in[0];   // x: [B,3] f32
    const float4* c4 = (const float4*)d_in[1];   // center: [B,3] f32
    float4* o4 = (float4*)d_out;

    int n_elems = in_sizes[0];            // B*3 = 25165824
    int n_f4 = n_elems / 4;               // 6291456 float4s per array
    int blocks = n_f4 / F4PT;             // 8192, exact (no tail)

    circle_proj_kernel<<<blocks, TPB>>>(x4, c4, o4);
}